// round 3
// baseline (speedup 1.0000x reference)
#include <cuda_runtime.h>
#include <cstdint>

#define HID 256
#define NNODE 64
#define NGRAPH 128
#define NROWS 8192   /* NGRAPH*NNODE */
#define DIN 512
#define NHEAD 4
#define CH 64

// ---------------- scratch (no allocations allowed -> __device__ globals) ----
__device__ float g_h0[NROWS * HID];   // projected input (pre-layers, unmasked)
__device__ float g_hw[NROWS * HID];   // working hidden state
__device__ float g_xl[NROWS * HID];
__device__ float g_xr[NROWS * HID];
__device__ float g_go[NROWS * HID];   // gat layer raw output
__device__ unsigned long long g_maskbits[NGRAPH];
__device__ int g_keep[NGRAPH];

// ---------------- f32x2 packed math (Blackwell FFMA2, PTX-only) -------------
#define PACK2(u, lo, hi) asm("mov.b64 %0, {%1, %2};" : "=l"(u) : "f"(lo), "f"(hi))
#define UNPACK2(lo, hi, u) asm("mov.b64 {%0, %1}, %2;" : "=f"(lo), "=f"(hi) : "l"(u))
#define FMA2(d, a, b) asm("fma.rn.f32x2 %0, %1, %2, %0;" : "+l"(d) : "l"(a), "l"(b))

// ---------------- mask decode (dtype-robust) --------------------------------
// person_mask arrives as bool -> unknown wire dtype. Detect uint8 / int32 /
// float32 from byte patterns in the first 8192 bytes (always in-bounds).
__global__ void decode_mask_kernel(const unsigned char* __restrict__ pm) {
    __shared__ int flags[4];
    __shared__ unsigned char sm[NROWS];
    int tid = threadIdx.x;
    if (tid < 4) flags[tid] = 0;
    __syncthreads();
    int loc0 = 0, loc1 = 0, loc23 = 0;
    for (int i = tid; i < NROWS; i += 256) {
        if (pm[i]) {
            int r = i & 3;
            if (r == 0) loc0 = 1;
            else if (r == 1) loc1 = 1;
            else loc23 = 1;
        }
    }
    if (loc0) atomicOr(&flags[0], 1);
    if (loc1) atomicOr(&flags[1], 1);
    if (loc23) atomicOr(&flags[2], 1);
    __syncthreads();
    // uint8: random nonzeros at pos%4==1.  int32: nonzeros only at pos%4==0.
    // float32 (1.0f = 00 00 80 3f): nonzeros only at pos%4 in {2,3}.
    int mode;
    if (flags[1]) mode = 0;          // uint8
    else if (flags[0]) mode = 1;     // int32
    else if (flags[2]) mode = 2;     // float32
    else mode = 0;                   // all-zero mask: any view works
    for (int i = tid; i < NROWS; i += 256) {
        unsigned char m;
        if (mode == 0)      m = (pm[i] != 0);
        else if (mode == 1) m = (((const int*)pm)[i] != 0);
        else                m = (((const float*)pm)[i] != 0.0f);
        sm[i] = m;
    }
    __syncthreads();
    if (tid < NGRAPH) {
        unsigned long long mb = 0ull;
        int cnt = 0;
        #pragma unroll
        for (int n = 0; n < 64; n++) {
            if (sm[tid * 64 + n]) { mb |= (1ull << n); cnt++; }
        }
        g_maskbits[tid] = mb;
        g_keep[tid] = (cnt > 1) ? 1 : 0;
    }
}

// ---------------- GEMM: C[M,Nc] = A[M,K] @ W[K,Nc] + bias -------------------
// Tile 64x128, BK=16, 256 threads, 4x8 microtile via FFMA2. M%64==0, Nc%128==0,
// K%16==0 for all call sites (no bounds checks needed).
__global__ __launch_bounds__(256) void gemm_bias_kernel(
    const float* __restrict__ A, const float* __restrict__ W,
    const float* __restrict__ bias, float* __restrict__ C,
    int M, int K, int Nc) {
    __shared__ float As[16][64];    // transposed A tile: As[k][m]
    __shared__ float Bs[16][128];
    int tid = threadIdx.x;
    int bm = blockIdx.x * 64;
    int bn = blockIdx.y * 128;
    int tx = tid & 15, ty = tid >> 4;
    int arow = tid >> 2;
    int ak = (tid & 3) << 2;
    int brow = tid >> 4;
    int bcol = (tid & 15) << 3;

    unsigned long long acc[4][4];
    #pragma unroll
    for (int r = 0; r < 4; r++)
        #pragma unroll
        for (int p = 0; p < 4; p++) acc[r][p] = 0ull;

    const float* Aptr = A + (size_t)(bm + arow) * K + ak;
    const float* Wptr = W + (size_t)brow * Nc + bn + bcol;

    for (int k0 = 0; k0 < K; k0 += 16) {
        float4 av = *(const float4*)(Aptr + k0);
        float4 bv0 = *(const float4*)(Wptr + (size_t)k0 * Nc);
        float4 bv1 = *(const float4*)(Wptr + (size_t)k0 * Nc + 4);
        As[ak + 0][arow] = av.x;
        As[ak + 1][arow] = av.y;
        As[ak + 2][arow] = av.z;
        As[ak + 3][arow] = av.w;
        *(float4*)&Bs[brow][bcol] = bv0;
        *(float4*)&Bs[brow][bcol + 4] = bv1;
        __syncthreads();
        #pragma unroll
        for (int k = 0; k < 16; k++) {
            float4 a4 = *(const float4*)&As[k][ty << 2];
            unsigned long long ad0, ad1, ad2, ad3;
            PACK2(ad0, a4.x, a4.x);
            PACK2(ad1, a4.y, a4.y);
            PACK2(ad2, a4.z, a4.z);
            PACK2(ad3, a4.w, a4.w);
            const ulonglong2* bp = (const ulonglong2*)&Bs[k][tx << 3];
            ulonglong2 b01 = bp[0];
            ulonglong2 b23 = bp[1];
            FMA2(acc[0][0], ad0, b01.x); FMA2(acc[0][1], ad0, b01.y);
            FMA2(acc[0][2], ad0, b23.x); FMA2(acc[0][3], ad0, b23.y);
            FMA2(acc[1][0], ad1, b01.x); FMA2(acc[1][1], ad1, b01.y);
            FMA2(acc[1][2], ad1, b23.x); FMA2(acc[1][3], ad1, b23.y);
            FMA2(acc[2][0], ad2, b01.x); FMA2(acc[2][1], ad2, b01.y);
            FMA2(acc[2][2], ad2, b23.x); FMA2(acc[2][3], ad2, b23.y);
            FMA2(acc[3][0], ad3, b01.x); FMA2(acc[3][1], ad3, b01.y);
            FMA2(acc[3][2], ad3, b23.x); FMA2(acc[3][3], ad3, b23.y);
        }
        __syncthreads();
    }

    const float* bptr = bias + bn + (tx << 3);
    #pragma unroll
    for (int r = 0; r < 4; r++) {
        int row = bm + (ty << 2) + r;
        float* cp = C + (size_t)row * Nc + bn + (tx << 3);
        #pragma unroll
        for (int p = 0; p < 4; p++) {
            float lo, hi;
            UNPACK2(lo, hi, acc[r][p]);
            cp[2 * p]     = lo + bptr[2 * p];
            cp[2 * p + 1] = hi + bptr[2 * p + 1];
        }
    }
}

// ---------------- GATv2 attention: one block per (graph, head) --------------
// smem exactly 48KB static. e-phase uses skewed c-index -> conflict-free LDS.
__global__ __launch_bounds__(256) void attn_kernel(
    const float* __restrict__ xl, const float* __restrict__ xr,
    const float* __restrict__ att, float* __restrict__ go) {
    __shared__ float s_xl[64 * 64];
    __shared__ float s_xr[64 * 64];
    __shared__ float s_e[64 * 64];
    int g = blockIdx.x, h = blockIdx.y;
    int tid = threadIdx.x;
    int w = tid >> 5, l = tid & 31;
    int rowbase = g * 64;
    int hoff = h * 64;
    const float* attv = att + (h << 6);

    for (int idx = tid; idx < 4096; idx += 256) {
        int j = idx >> 6, c = idx & 63;
        size_t gidx = (size_t)(rowbase + j) * HID + hoff + c;
        s_xl[idx] = xl[gidx];
        s_xr[idx] = xr[gidx];
    }
    unsigned long long mb = g_maskbits[g];
    __syncthreads();

    // ---- e-phase: warp w owns target rows i in [8w, 8w+8); lane owns j=l,l+32
    int ibase = w << 3;
    float acc0[8], acc1[8];
    #pragma unroll
    for (int p = 0; p < 8; p++) { acc0[p] = 0.f; acc1[p] = 0.f; }
    #pragma unroll 4
    for (int t = 0; t < 64; t++) {
        int c = (t + l) & 63;          // skew -> all smem banks distinct per lane
        float a = __ldg(&attv[c]);
        float x1 = s_xl[(l << 6) + c];
        float x2 = s_xl[((l + 32) << 6) + c];
        #pragma unroll
        for (int p = 0; p < 8; p++) {
            float xrv = s_xr[((ibase + p) << 6) + c];
            float s1 = xrv + x1;
            float s2 = xrv + x2;
            s1 = fmaxf(s1, 0.f) + 0.2f * fminf(s1, 0.f);   // leaky_relu(0.2)
            s2 = fmaxf(s2, 0.f) + 0.2f * fminf(s2, 0.f);
            acc0[p] = fmaf(a, s1, acc0[p]);
            acc1[p] = fmaf(a, s2, acc1[p]);
        }
    }
    #pragma unroll
    for (int p = 0; p < 8; p++) {
        int i = ibase + p;
        bool mi = (mb >> i) & 1ull;
        int j1 = l, j2 = l + 32;
        bool a1 = (i == j1) || (mi && ((mb >> j1) & 1ull));
        bool a2 = (i == j2) || (mi && ((mb >> j2) & 1ull));
        s_e[(i << 6) + j1] = a1 ? acc0[p] : -1e30f;
        s_e[(i << 6) + j2] = a2 ? acc1[p] : -1e30f;
    }
    __syncwarp();

    // ---- softmax over j for each owned row (warp-local)
    #pragma unroll
    for (int p = 0; p < 8; p++) {
        int i = ibase + p;
        float v1 = s_e[(i << 6) + l];
        float v2 = s_e[(i << 6) + l + 32];
        float mx = fmaxf(v1, v2);
        #pragma unroll
        for (int o = 16; o > 0; o >>= 1)
            mx = fmaxf(mx, __shfl_xor_sync(0xffffffffu, mx, o));
        float e1 = expf(v1 - mx);      // masked (-1e30) -> exp underflows to 0
        float e2 = expf(v2 - mx);
        float s = e1 + e2;
        #pragma unroll
        for (int o = 16; o > 0; o >>= 1)
            s += __shfl_xor_sync(0xffffffffu, s, o);
        float inv = 1.0f / s;
        s_e[(i << 6) + l] = e1 * inv;
        s_e[(i << 6) + l + 32] = e2 * inv;
    }
    __syncwarp();

    // ---- AV: out[i][c] = sum_j alpha[i][j] * xl[j][c]; lane owns c=l,l+32
    float o0[8], o1[8];
    #pragma unroll
    for (int p = 0; p < 8; p++) { o0[p] = 0.f; o1[p] = 0.f; }
    for (int j = 0; j < 64; j++) {
        float x1 = s_xl[(j << 6) + l];         // bank = l: conflict-free
        float x2 = s_xl[(j << 6) + l + 32];
        #pragma unroll
        for (int p = 0; p < 8; p++) {
            float al = s_e[((ibase + p) << 6) + j];   // broadcast
            o0[p] = fmaf(al, x1, o0[p]);
            o1[p] = fmaf(al, x2, o1[p]);
        }
    }
    #pragma unroll
    for (int p = 0; p < 8; p++) {
        int i = ibase + p;
        size_t gidx = (size_t)(rowbase + i) * HID + hoff;
        go[gidx + l] = o0[p];
        go[gidx + l + 32] = o1[p];
    }
}

// ---------------- epilogue: bias + ELU + LayerNorm + residual + mask --------
__device__ __forceinline__ float block_reduce_sum_256(float v, float* red, int tid) {
    __syncthreads();   // protect red[] reuse between calls
    #pragma unroll
    for (int o = 16; o > 0; o >>= 1)
        v += __shfl_xor_sync(0xffffffffu, v, o);
    if ((tid & 31) == 0) red[tid >> 5] = v;
    __syncthreads();
    float tot = 0.f;
    #pragma unroll
    for (int i = 0; i < 8; i++) tot += red[i];
    return tot;
}

__global__ __launch_bounds__(256) void epilogue_kernel(
    const float* __restrict__ go, const float* __restrict__ resid,
    const float* __restrict__ ob, const float* __restrict__ lns,
    const float* __restrict__ lnb, float* __restrict__ outp,
    int final_layer, const float* __restrict__ h0) {
    __shared__ float red[8];
    int row = blockIdx.x;
    int c = threadIdx.x;
    size_t idx = (size_t)row * HID + c;
    float v = go[idx] + ob[c];
    v = (v > 0.f) ? v : expm1f(v);                 // ELU (alpha=1)
    float sum = block_reduce_sum_256(v, red, c);
    float mu = sum * (1.0f / 256.0f);
    float d = v - mu;
    float s2 = block_reduce_sum_256(d * d, red, c);
    float var = s2 * (1.0f / 256.0f);
    float y = d * rsqrtf(var + 1e-5f) * lns[c] + lnb[c] + resid[idx];
    int gi = row >> 6, node = row & 63;
    float hv = ((g_maskbits[gi] >> node) & 1ull) ? y : 0.f;
    if (final_layer)
        outp[idx] = g_keep[gi] ? hv : h0[idx];     // graphs with <=1 node: passthrough
    else
        outp[idx] = hv;
}

// ---------------- launch ----------------------------------------------------
extern "C" void kernel_launch(void* const* d_in, const int* in_sizes, int n_in,
                              void* d_out, int out_size) {
    (void)in_sizes; (void)n_in; (void)out_size;
    const float* x   = (const float*)d_in[0];
    const unsigned char* pm = (const unsigned char*)d_in[1];
    const float* W_in = (const float*)d_in[2];
    const float* b_in = (const float*)d_in[3];
    const float* Wl  = (const float*)d_in[4];
    const float* bl  = (const float*)d_in[5];
    const float* Wr  = (const float*)d_in[6];
    const float* br  = (const float*)d_in[7];
    const float* att = (const float*)d_in[8];
    const float* ob  = (const float*)d_in[9];
    const float* lns = (const float*)d_in[10];
    const float* lnb = (const float*)d_in[11];
    float* out = (float*)d_out;

    float *h0, *hw, *xl, *xr, *go;
    cudaGetSymbolAddress((void**)&h0, g_h0);
    cudaGetSymbolAddress((void**)&hw, g_hw);
    cudaGetSymbolAddress((void**)&xl, g_xl);
    cudaGetSymbolAddress((void**)&xr, g_xr);
    cudaGetSymbolAddress((void**)&go, g_go);

    decode_mask_kernel<<<1, 256>>>(pm);

    dim3 ggrid(NROWS / 64, HID / 128);   // (128, 2)
    gemm_bias_kernel<<<ggrid, 256>>>(x, W_in, b_in, h0, NROWS, DIN, HID);

    for (int li = 0; li < 2; li++) {
        const float* hin = li ? hw : h0;
        gemm_bias_kernel<<<ggrid, 256>>>(hin, Wl + li * HID * HID, bl + li * HID,
                                         xl, NROWS, HID, HID);
        gemm_bias_kernel<<<ggrid, 256>>>(hin, Wr + li * HID * HID, br + li * HID,
                                         xr, NROWS, HID, HID);
        attn_kernel<<<dim3(NGRAPH, NHEAD), 256>>>(xl, xr, att + li * NHEAD * CH, go);
        epilogue_kernel<<<NROWS, 256>>>(go, hin, ob + li * HID, lns + li * HID,
                                        lnb + li * HID,
                                        (li == 1) ? out : hw, (li == 1) ? 1 : 0, h0);
    }
}

// round 4
// speedup vs baseline: 1.7790x; 1.7790x over previous
#include <cuda_runtime.h>
#include <cstdint>

#define HID 256
#define NNODE 64
#define NGRAPH 128
#define NROWS 8192   /* NGRAPH*NNODE */
#define DIN 512
#define NHEAD 4
#define CH 64

// ---------------- scratch (no allocations allowed -> __device__ globals) ----
__device__ float g_h0[NROWS * HID];   // projected input (pre-layers, unmasked)
__device__ float g_hw[NROWS * HID];   // working hidden state
__device__ float g_xl[NROWS * HID];
__device__ float g_xr[NROWS * HID];
__device__ float g_go[NROWS * HID];   // gat layer raw output
__device__ unsigned long long g_maskbits[NGRAPH];
__device__ int g_keep[NGRAPH];

// ---------------- f32x2 packed math (Blackwell FFMA2, PTX-only) -------------
#define PACK2(u, lo, hi) asm("mov.b64 %0, {%1, %2};" : "=l"(u) : "f"(lo), "f"(hi))
#define UNPACK2(lo, hi, u) asm("mov.b64 {%0, %1}, %2;" : "=f"(lo), "=f"(hi) : "l"(u))
#define FMA2ACC(d, a, b) asm("fma.rn.f32x2 %0, %1, %2, %0;" : "+l"(d) : "l"(a), "l"(b))
#define ADD2(d, a, b) asm("add.rn.f32x2 %0, %1, %2;" : "=l"(d) : "l"(a), "l"(b))
#define MUL2(d, a, b) asm("mul.rn.f32x2 %0, %1, %2;" : "=l"(d) : "l"(a), "l"(b))
#define FMA2G(d, a, b, c) asm("fma.rn.f32x2 %0, %1, %2, %3;" : "=l"(d) : "l"(a), "l"(b), "l"(c))

// ---------------- mask decode (dtype-robust) --------------------------------
__global__ void decode_mask_kernel(const unsigned char* __restrict__ pm) {
    __shared__ int flags[4];
    __shared__ unsigned char sm[NROWS];
    int tid = threadIdx.x;
    if (tid < 4) flags[tid] = 0;
    __syncthreads();
    int loc0 = 0, loc1 = 0, loc23 = 0;
    for (int i = tid; i < NROWS; i += 256) {
        if (pm[i]) {
            int r = i & 3;
            if (r == 0) loc0 = 1;
            else if (r == 1) loc1 = 1;
            else loc23 = 1;
        }
    }
    if (loc0) atomicOr(&flags[0], 1);
    if (loc1) atomicOr(&flags[1], 1);
    if (loc23) atomicOr(&flags[2], 1);
    __syncthreads();
    int mode;
    if (flags[1]) mode = 0;          // uint8
    else if (flags[0]) mode = 1;     // int32
    else if (flags[2]) mode = 2;     // float32
    else mode = 0;
    for (int i = tid; i < NROWS; i += 256) {
        unsigned char m;
        if (mode == 0)      m = (pm[i] != 0);
        else if (mode == 1) m = (((const int*)pm)[i] != 0);
        else                m = (((const float*)pm)[i] != 0.0f);
        sm[i] = m;
    }
    __syncthreads();
    if (tid < NGRAPH) {
        unsigned long long mb = 0ull;
        int cnt = 0;
        #pragma unroll
        for (int n = 0; n < 64; n++) {
            if (sm[tid * 64 + n]) { mb |= (1ull << n); cnt++; }
        }
        g_maskbits[tid] = mb;
        g_keep[tid] = (cnt > 1) ? 1 : 0;
    }
}

// ---------------- GEMM: 128x128 tile, BK=8, 8x8 microtile, double-buffered --
// C[M,256] = A[M,K] @ W[K,256] + bias.  grid.y selects (W0,C0) vs (W1,C1) and
// the 128-col half, so an xl/xr projection pair is ONE launch (grid.y = 4).
__global__ __launch_bounds__(256, 2) void gemm128_kernel(
    const float* __restrict__ A,
    const float* __restrict__ W0, const float* __restrict__ W1,
    const float* __restrict__ bias0, const float* __restrict__ bias1,
    float* __restrict__ C0, float* __restrict__ C1, int K) {
    __shared__ float As[2][8][132];   // padded: conflict-free transposed stores
    __shared__ float Bs[2][8][128];
    const int Nc = 256;
    int tid = threadIdx.x;
    int bm = blockIdx.x << 7;
    int sel = blockIdx.y >> 1;
    int bn = (blockIdx.y & 1) << 7;
    const float* W = sel ? W1 : W0;
    const float* bias = sel ? bias1 : bias0;
    float* C = sel ? C1 : C0;

    int tx = tid & 15, ty = tid >> 4;
    int arow = tid >> 1, akq = (tid & 1) << 2;
    int brow = tid >> 5, bcol = (tid & 31) << 2;
    const float* Ag = A + (size_t)(bm + arow) * K + akq;
    const float* Bg = W + (size_t)brow * Nc + bn + bcol;

    unsigned long long acc[8][4];
    #pragma unroll
    for (int r = 0; r < 8; r++)
        #pragma unroll
        for (int p = 0; p < 4; p++) acc[r][p] = 0ull;

    // prologue: stage tile 0
    float4 ra = *(const float4*)Ag;
    float4 rb = *(const float4*)Bg;
    As[0][akq + 0][arow] = ra.x;
    As[0][akq + 1][arow] = ra.y;
    As[0][akq + 2][arow] = ra.z;
    As[0][akq + 3][arow] = ra.w;
    *(float4*)&Bs[0][brow][bcol] = rb;
    __syncthreads();

    int KB = K >> 3;
    int s = 0;
    for (int kb = 0; kb < KB; kb++) {
        if (kb + 1 < KB) {
            ra = *(const float4*)(Ag + ((kb + 1) << 3));
            rb = *(const float4*)(Bg + (size_t)((kb + 1) << 3) * Nc);
        }
        #pragma unroll
        for (int k = 0; k < 8; k++) {
            float4 a0 = *(const float4*)&As[s][k][ty << 2];
            float4 a1 = *(const float4*)&As[s][k][64 + (ty << 2)];
            float4 b0 = *(const float4*)&Bs[s][k][tx << 2];
            float4 b1 = *(const float4*)&Bs[s][k][64 + (tx << 2)];
            unsigned long long bp0, bp1, bp2, bp3;
            PACK2(bp0, b0.x, b0.y); PACK2(bp1, b0.z, b0.w);
            PACK2(bp2, b1.x, b1.y); PACK2(bp3, b1.z, b1.w);
            unsigned long long ad[8];
            PACK2(ad[0], a0.x, a0.x); PACK2(ad[1], a0.y, a0.y);
            PACK2(ad[2], a0.z, a0.z); PACK2(ad[3], a0.w, a0.w);
            PACK2(ad[4], a1.x, a1.x); PACK2(ad[5], a1.y, a1.y);
            PACK2(ad[6], a1.z, a1.z); PACK2(ad[7], a1.w, a1.w);
            #pragma unroll
            for (int r = 0; r < 8; r++) {
                FMA2ACC(acc[r][0], ad[r], bp0);
                FMA2ACC(acc[r][1], ad[r], bp1);
                FMA2ACC(acc[r][2], ad[r], bp2);
                FMA2ACC(acc[r][3], ad[r], bp3);
            }
        }
        if (kb + 1 < KB) {
            int sn = s ^ 1;
            As[sn][akq + 0][arow] = ra.x;
            As[sn][akq + 1][arow] = ra.y;
            As[sn][akq + 2][arow] = ra.z;
            As[sn][akq + 3][arow] = ra.w;
            *(float4*)&Bs[sn][brow][bcol] = rb;
            __syncthreads();
            s = sn;
        }
    }

    // epilogue: bias + store (coalesced float4s)
    float4 bb0 = *(const float4*)(bias + bn + (tx << 2));
    float4 bb1 = *(const float4*)(bias + bn + 64 + (tx << 2));
    #pragma unroll
    for (int r = 0; r < 8; r++) {
        int mrow = bm + ((r < 4) ? ((ty << 2) + r) : (64 + (ty << 2) + r - 4));
        float* cp = C + (size_t)mrow * Nc + bn;
        float4 o0, o1;
        UNPACK2(o0.x, o0.y, acc[r][0]); UNPACK2(o0.z, o0.w, acc[r][1]);
        UNPACK2(o1.x, o1.y, acc[r][2]); UNPACK2(o1.z, o1.w, acc[r][3]);
        o0.x += bb0.x; o0.y += bb0.y; o0.z += bb0.z; o0.w += bb0.w;
        o1.x += bb1.x; o1.y += bb1.y; o1.z += bb1.z; o1.w += bb1.w;
        *(float4*)(cp + (tx << 2)) = o0;
        *(float4*)(cp + 64 + (tx << 2)) = o1;
    }
}

// ---------------- GATv2 attention: one block per (graph, head) --------------
// e-phase packed f32x2: leaky_relu_0.2(x) = 0.6x + 0.4|x| (|.| = 64-bit AND).
__global__ __launch_bounds__(256) void attn_kernel(
    const float* __restrict__ xl, const float* __restrict__ xr,
    const float* __restrict__ att, float* __restrict__ go) {
    __shared__ float s_xl[64 * 64];
    __shared__ float s_xr[64 * 64];
    __shared__ float s_e[64 * 64];
    int g = blockIdx.x, h = blockIdx.y;
    int tid = threadIdx.x;
    int w = tid >> 5, l = tid & 31;
    int rowbase = g * 64;
    int hoff = h * 64;
    const float2* attv2 = (const float2*)(att + (h << 6));

    for (int idx = tid; idx < 4096; idx += 256) {
        int j = idx >> 6, c = idx & 63;
        size_t gidx = (size_t)(rowbase + j) * HID + hoff + c;
        s_xl[idx] = xl[gidx];
        s_xr[idx] = xr[gidx];
    }
    unsigned long long mb = g_maskbits[g];
    __syncthreads();

    const unsigned long long ABS2 = 0x7FFFFFFF7FFFFFFFull;
    const unsigned long long K06 = 0x3F19999A3F19999Aull;  // (0.6f, 0.6f)
    const unsigned long long K04 = 0x3ECCCCCD3ECCCCCDull;  // (0.4f, 0.4f)

    // ---- e-phase: warp w owns target rows i in [8w,8w+8); lane owns j=l,l+32
    int ibase = w << 3;
    unsigned long long acc0[8], acc1[8];
    #pragma unroll
    for (int p = 0; p < 8; p++) { acc0[p] = 0ull; acc1[p] = 0ull; }
    #pragma unroll 4
    for (int t = 0; t < 32; t++) {
        int cp = (t + l) & 31;        // skew -> conflict-free banks
        int c = cp << 1;
        float2 af = __ldg(&attv2[cp]);
        unsigned long long a2; PACK2(a2, af.x, af.y);
        unsigned long long x1 = *(const unsigned long long*)&s_xl[(l << 6) + c];
        unsigned long long x2 = *(const unsigned long long*)&s_xl[((l + 32) << 6) + c];
        #pragma unroll
        for (int p = 0; p < 8; p++) {
            unsigned long long xr2 =
                *(const unsigned long long*)&s_xr[((ibase + p) << 6) + c];
            unsigned long long s1, s2, t1, t2, u1, u2, lr1, lr2;
            ADD2(s1, xr2, x1);
            ADD2(s2, xr2, x2);
            t1 = s1 & ABS2;
            t2 = s2 & ABS2;
            MUL2(u1, t1, K04);
            MUL2(u2, t2, K04);
            FMA2G(lr1, s1, K06, u1);
            FMA2G(lr2, s2, K06, u2);
            FMA2ACC(acc0[p], a2, lr1);
            FMA2ACC(acc1[p], a2, lr2);
        }
    }
    #pragma unroll
    for (int p = 0; p < 8; p++) {
        int i = ibase + p;
        bool mi = (mb >> i) & 1ull;
        int j1 = l, j2 = l + 32;
        bool a1 = (i == j1) || (mi && ((mb >> j1) & 1ull));
        bool a2 = (i == j2) || (mi && ((mb >> j2) & 1ull));
        float lo, hi;
        UNPACK2(lo, hi, acc0[p]);
        float e1 = lo + hi;
        UNPACK2(lo, hi, acc1[p]);
        float e2 = lo + hi;
        s_e[(i << 6) + j1] = a1 ? e1 : -1e30f;
        s_e[(i << 6) + j2] = a2 ? e2 : -1e30f;
    }
    __syncwarp();

    // ---- softmax over j for each owned row (warp-local)
    #pragma unroll
    for (int p = 0; p < 8; p++) {
        int i = ibase + p;
        float v1 = s_e[(i << 6) + l];
        float v2 = s_e[(i << 6) + l + 32];
        float mx = fmaxf(v1, v2);
        #pragma unroll
        for (int o = 16; o > 0; o >>= 1)
            mx = fmaxf(mx, __shfl_xor_sync(0xffffffffu, mx, o));
        float e1 = expf(v1 - mx);      // masked (-1e30) -> exp underflows to 0
        float e2 = expf(v2 - mx);
        float sv = e1 + e2;
        #pragma unroll
        for (int o = 16; o > 0; o >>= 1)
            sv += __shfl_xor_sync(0xffffffffu, sv, o);
        float inv = 1.0f / sv;
        s_e[(i << 6) + l] = e1 * inv;
        s_e[(i << 6) + l + 32] = e2 * inv;
    }
    __syncwarp();

    // ---- AV: out[i][c] = sum_j alpha[i][j] * xl[j][c]; lane owns c=l,l+32
    float o0[8], o1[8];
    #pragma unroll
    for (int p = 0; p < 8; p++) { o0[p] = 0.f; o1[p] = 0.f; }
    for (int j = 0; j < 64; j++) {
        float x1 = s_xl[(j << 6) + l];
        float x2 = s_xl[(j << 6) + l + 32];
        #pragma unroll
        for (int p = 0; p < 8; p++) {
            float al = s_e[((ibase + p) << 6) + j];   // broadcast
            o0[p] = fmaf(al, x1, o0[p]);
            o1[p] = fmaf(al, x2, o1[p]);
        }
    }
    #pragma unroll
    for (int p = 0; p < 8; p++) {
        int i = ibase + p;
        size_t gidx = (size_t)(rowbase + i) * HID + hoff;
        go[gidx + l] = o0[p];
        go[gidx + l + 32] = o1[p];
    }
}

// ---------------- epilogue: bias + ELU + LayerNorm + residual + mask --------
__device__ __forceinline__ float block_reduce_sum_256(float v, float* red, int tid) {
    __syncthreads();
    #pragma unroll
    for (int o = 16; o > 0; o >>= 1)
        v += __shfl_xor_sync(0xffffffffu, v, o);
    if ((tid & 31) == 0) red[tid >> 5] = v;
    __syncthreads();
    float tot = 0.f;
    #pragma unroll
    for (int i = 0; i < 8; i++) tot += red[i];
    return tot;
}

__global__ __launch_bounds__(256) void epilogue_kernel(
    const float* __restrict__ go, const float* __restrict__ resid,
    const float* __restrict__ ob, const float* __restrict__ lns,
    const float* __restrict__ lnb, float* __restrict__ outp,
    int final_layer, const float* __restrict__ h0) {
    __shared__ float red[8];
    int row = blockIdx.x;
    int c = threadIdx.x;
    size_t idx = (size_t)row * HID + c;
    float v = go[idx] + ob[c];
    v = (v > 0.f) ? v : expm1f(v);                 // ELU (alpha=1)
    float sum = block_reduce_sum_256(v, red, c);
    float mu = sum * (1.0f / 256.0f);
    float d = v - mu;
    float s2 = block_reduce_sum_256(d * d, red, c);
    float var = s2 * (1.0f / 256.0f);
    float y = d * rsqrtf(var + 1e-5f) * lns[c] + lnb[c] + resid[idx];
    int gi = row >> 6, node = row & 63;
    float hv = ((g_maskbits[gi] >> node) & 1ull) ? y : 0.f;
    if (final_layer)
        outp[idx] = g_keep[gi] ? hv : h0[idx];
    else
        outp[idx] = hv;
}

// ---------------- launch ----------------------------------------------------
extern "C" void kernel_launch(void* const* d_in, const int* in_sizes, int n_in,
                              void* d_out, int out_size) {
    (void)in_sizes; (void)n_in; (void)out_size;
    const float* x   = (const float*)d_in[0];
    const unsigned char* pm = (const unsigned char*)d_in[1];
    const float* W_in = (const float*)d_in[2];
    const float* b_in = (const float*)d_in[3];
    const float* Wl  = (const float*)d_in[4];
    const float* bl  = (const float*)d_in[5];
    const float* Wr  = (const float*)d_in[6];
    const float* br  = (const float*)d_in[7];
    const float* att = (const float*)d_in[8];
    const float* ob  = (const float*)d_in[9];
    const float* lns = (const float*)d_in[10];
    const float* lnb = (const float*)d_in[11];
    float* out = (float*)d_out;

    float *h0, *hw, *xl, *xr, *go;
    cudaGetSymbolAddress((void**)&h0, g_h0);
    cudaGetSymbolAddress((void**)&hw, g_hw);
    cudaGetSymbolAddress((void**)&xl, g_xl);
    cudaGetSymbolAddress((void**)&xr, g_xr);
    cudaGetSymbolAddress((void**)&go, g_go);

    decode_mask_kernel<<<1, 256>>>(pm);

    // input projection: [8192,512]@[512,256]; grid.y=2 covers both col halves
    gemm128_kernel<<<dim3(NROWS / 128, 2), 256>>>(
        x, W_in, W_in, b_in, b_in, h0, h0, DIN);

    for (int li = 0; li < 2; li++) {
        const float* hin = li ? hw : h0;
        // fused xl/xr projection pair: one launch, grid.y=4
        gemm128_kernel<<<dim3(NROWS / 128, 4), 256>>>(
            hin, Wl + li * HID * HID, Wr + li * HID * HID,
            bl + li * HID, br + li * HID, xl, xr, HID);
        attn_kernel<<<dim3(NGRAPH, NHEAD), 256>>>(xl, xr, att + li * NHEAD * CH, go);
        epilogue_kernel<<<NROWS, 256>>>(go, hin, ob + li * HID, lns + li * HID,
                                        lnb + li * HID,
                                        (li == 1) ? out : hw, (li == 1) ? 1 : 0, h0);
    }
}

// round 5
// speedup vs baseline: 1.9326x; 1.0864x over previous
#include <cuda_runtime.h>
#include <cstdint>

#define HID 256
#define NNODE 64
#define NGRAPH 128
#define NROWS 8192   /* NGRAPH*NNODE */
#define DIN 512
#define NHEAD 4
#define CH 64

// ---------------- scratch (no allocations allowed -> __device__ globals) ----
__device__ float g_h0[NROWS * HID];   // projected input (pre-layers, unmasked)
__device__ float g_hw[NROWS * HID];   // working hidden state
__device__ float g_xl[NROWS * HID];
__device__ float g_xr[NROWS * HID];
__device__ float g_go[NROWS * HID];   // gat layer raw output
__device__ unsigned long long g_maskbits[NGRAPH];
__device__ int g_keep[NGRAPH];

// ---------------- f32x2 packed math (Blackwell FFMA2, PTX-only) -------------
#define PACK2(u, lo, hi) asm("mov.b64 %0, {%1, %2};" : "=l"(u) : "f"(lo), "f"(hi))
#define UNPACK2(lo, hi, u) asm("mov.b64 {%0, %1}, %2;" : "=f"(lo), "=f"(hi) : "l"(u))
#define FMA2ACC(d, a, b) asm("fma.rn.f32x2 %0, %1, %2, %0;" : "+l"(d) : "l"(a), "l"(b))
#define ADD2(d, a, b) asm("add.rn.f32x2 %0, %1, %2;" : "=l"(d) : "l"(a), "l"(b))

// ---------------- mask decode (dtype-robust) --------------------------------
__global__ void decode_mask_kernel(const unsigned char* __restrict__ pm) {
    __shared__ int flags[4];
    __shared__ unsigned char sm[NROWS];
    int tid = threadIdx.x;
    if (tid < 4) flags[tid] = 0;
    __syncthreads();
    int loc0 = 0, loc1 = 0, loc23 = 0;
    for (int i = tid; i < NROWS; i += 256) {
        if (pm[i]) {
            int r = i & 3;
            if (r == 0) loc0 = 1;
            else if (r == 1) loc1 = 1;
            else loc23 = 1;
        }
    }
    if (loc0) atomicOr(&flags[0], 1);
    if (loc1) atomicOr(&flags[1], 1);
    if (loc23) atomicOr(&flags[2], 1);
    __syncthreads();
    int mode;
    if (flags[1]) mode = 0;          // uint8
    else if (flags[0]) mode = 1;     // int32
    else if (flags[2]) mode = 2;     // float32
    else mode = 0;
    for (int i = tid; i < NROWS; i += 256) {
        unsigned char m;
        if (mode == 0)      m = (pm[i] != 0);
        else if (mode == 1) m = (((const int*)pm)[i] != 0);
        else                m = (((const float*)pm)[i] != 0.0f);
        sm[i] = m;
    }
    __syncthreads();
    if (tid < NGRAPH) {
        unsigned long long mb = 0ull;
        int cnt = 0;
        #pragma unroll
        for (int n = 0; n < 64; n++) {
            if (sm[tid * 64 + n]) { mb |= (1ull << n); cnt++; }
        }
        g_maskbits[tid] = mb;
        g_keep[tid] = (cnt > 1) ? 1 : 0;
    }
}

// ---------------- GEMM: 128x128 tile, BK=8, 8x8 microtile, double-buffered --
__global__ __launch_bounds__(256, 2) void gemm128_kernel(
    const float* __restrict__ A,
    const float* __restrict__ W0, const float* __restrict__ W1,
    const float* __restrict__ bias0, const float* __restrict__ bias1,
    float* __restrict__ C0, float* __restrict__ C1, int K) {
    __shared__ float As[2][8][132];
    __shared__ float Bs[2][8][128];
    const int Nc = 256;
    int tid = threadIdx.x;
    int bm = blockIdx.x << 7;
    int sel = blockIdx.y >> 1;
    int bn = (blockIdx.y & 1) << 7;
    const float* W = sel ? W1 : W0;
    const float* bias = sel ? bias1 : bias0;
    float* C = sel ? C1 : C0;

    int tx = tid & 15, ty = tid >> 4;
    int arow = tid >> 1, akq = (tid & 1) << 2;
    int brow = tid >> 5, bcol = (tid & 31) << 2;
    const float* Ag = A + (size_t)(bm + arow) * K + akq;
    const float* Bg = W + (size_t)brow * Nc + bn + bcol;

    unsigned long long acc[8][4];
    #pragma unroll
    for (int r = 0; r < 8; r++)
        #pragma unroll
        for (int p = 0; p < 4; p++) acc[r][p] = 0ull;

    float4 ra = *(const float4*)Ag;
    float4 rb = *(const float4*)Bg;
    As[0][akq + 0][arow] = ra.x;
    As[0][akq + 1][arow] = ra.y;
    As[0][akq + 2][arow] = ra.z;
    As[0][akq + 3][arow] = ra.w;
    *(float4*)&Bs[0][brow][bcol] = rb;
    __syncthreads();

    int KB = K >> 3;
    int s = 0;
    for (int kb = 0; kb < KB; kb++) {
        if (kb + 1 < KB) {
            ra = *(const float4*)(Ag + ((kb + 1) << 3));
            rb = *(const float4*)(Bg + (size_t)((kb + 1) << 3) * Nc);
        }
        #pragma unroll
        for (int k = 0; k < 8; k++) {
            float4 a0 = *(const float4*)&As[s][k][ty << 2];
            float4 a1 = *(const float4*)&As[s][k][64 + (ty << 2)];
            float4 b0 = *(const float4*)&Bs[s][k][tx << 2];
            float4 b1 = *(const float4*)&Bs[s][k][64 + (tx << 2)];
            unsigned long long bp0, bp1, bp2, bp3;
            PACK2(bp0, b0.x, b0.y); PACK2(bp1, b0.z, b0.w);
            PACK2(bp2, b1.x, b1.y); PACK2(bp3, b1.z, b1.w);
            unsigned long long ad[8];
            PACK2(ad[0], a0.x, a0.x); PACK2(ad[1], a0.y, a0.y);
            PACK2(ad[2], a0.z, a0.z); PACK2(ad[3], a0.w, a0.w);
            PACK2(ad[4], a1.x, a1.x); PACK2(ad[5], a1.y, a1.y);
            PACK2(ad[6], a1.z, a1.z); PACK2(ad[7], a1.w, a1.w);
            #pragma unroll
            for (int r = 0; r < 8; r++) {
                FMA2ACC(acc[r][0], ad[r], bp0);
                FMA2ACC(acc[r][1], ad[r], bp1);
                FMA2ACC(acc[r][2], ad[r], bp2);
                FMA2ACC(acc[r][3], ad[r], bp3);
            }
        }
        if (kb + 1 < KB) {
            int sn = s ^ 1;
            As[sn][akq + 0][arow] = ra.x;
            As[sn][akq + 1][arow] = ra.y;
            As[sn][akq + 2][arow] = ra.z;
            As[sn][akq + 3][arow] = ra.w;
            *(float4*)&Bs[sn][brow][bcol] = rb;
            __syncthreads();
            s = sn;
        }
    }

    float4 bb0 = *(const float4*)(bias + bn + (tx << 2));
    float4 bb1 = *(const float4*)(bias + bn + 64 + (tx << 2));
    #pragma unroll
    for (int r = 0; r < 8; r++) {
        int mrow = bm + ((r < 4) ? ((ty << 2) + r) : (64 + (ty << 2) + r - 4));
        float* cp = C + (size_t)mrow * Nc + bn;
        float4 o0, o1;
        UNPACK2(o0.x, o0.y, acc[r][0]); UNPACK2(o0.z, o0.w, acc[r][1]);
        UNPACK2(o1.x, o1.y, acc[r][2]); UNPACK2(o1.z, o1.w, acc[r][3]);
        o0.x += bb0.x; o0.y += bb0.y; o0.z += bb0.z; o0.w += bb0.w;
        o1.x += bb1.x; o1.y += bb1.y; o1.z += bb1.z; o1.w += bb1.w;
        *(float4*)(cp + (tx << 2)) = o0;
        *(float4*)(cp + 64 + (tx << 2)) = o1;
    }
}

// ---------------- GATv2 attention v2: masked-node compaction ----------------
// Unmasked target i: softmax is one-hot over self -> out_i = xl_i (exact).
// Masked i: allowed j = ALL masked nodes -> dense MxM attention on the
// compacted list. e decomposition: leaky02(s) = 0.6 s + 0.4|s|, so
//   e_ij = 0.6*(a.xr_i + a.xl_j) + 0.4*sum_c a_c*|xr_i[c]+xl_j[c]|
// rank-1 part precomputed per node; inner loop = ADD2+AND+FMA2 per 2 chans.
__global__ __launch_bounds__(256) void attn_kernel(
    const float* __restrict__ xl, const float* __restrict__ xr,
    const float* __restrict__ att, float* __restrict__ go) {
    __shared__ float s_xlc[64 * 64];
    __shared__ float s_xrc[64 * 64];
    __shared__ float s_alpha[64 * 64];
    __shared__ float s_att[64];
    __shared__ float s_dl[64], s_dr[64];
    __shared__ int s_list[64];
    __shared__ int s_Msh;

    int g = blockIdx.x, h = blockIdx.y;
    int tid = threadIdx.x, w = tid >> 5, l = tid & 31;
    int rowbase = g << 6, hoff = h << 6;
    unsigned long long mb = g_maskbits[g];

    if (tid == 0) {
        int m = 0;
        unsigned long long b = mb;
        while (b) { s_list[m++] = __ffsll(b) - 1; b &= b - 1; }
        s_Msh = m;
    }
    if (tid < 64) s_att[tid] = att[hoff + tid];
    __syncthreads();
    int M = s_Msh;

    // pass-through for unmasked targets: out_i = xl_i (independent of rest)
    for (int idx = tid; idx < 4096; idx += 256) {
        int i = idx >> 6, c = idx & 63;
        if (!((mb >> i) & 1ull)) {
            size_t gidx = (size_t)(rowbase + i) * HID + hoff + c;
            go[gidx] = xl[gidx];
        }
    }

    // compact-load masked rows
    for (int idx = tid; idx < (M << 6); idx += 256) {
        int m = idx >> 6, c = idx & 63;
        size_t gidx = (size_t)(rowbase + s_list[m]) * HID + hoff + c;
        s_xlc[idx] = xl[gidx];
        s_xrc[idx] = xr[gidx];
    }
    __syncthreads();

    // per-node dots (skewed c -> conflict-free)
    if (tid < M) {
        float dl = 0.f, dr = 0.f;
        #pragma unroll 8
        for (int t = 0; t < 64; t++) {
            int c = (t + tid) & 63;
            float a = s_att[c];
            dl = fmaf(a, s_xlc[(tid << 6) + c], dl);
            dr = fmaf(a, s_xrc[(tid << 6) + c], dr);
        }
        s_dl[tid] = dl;
        s_dr[tid] = dr;
    }
    __syncthreads();

    const unsigned long long ABS2 = 0x7FFFFFFF7FFFFFFFull;
    bool v1 = (l < M), v2 = (l + 32 < M);
    float dl1 = v1 ? s_dl[l] : 0.f;
    float dl2 = v2 ? s_dl[l + 32] : 0.f;

    // warp w owns rows mi with mi % 8 == w; process 2 rows/iter to share loads
    for (int mi0 = w; mi0 < M; mi0 += 16) {
        int miA = mi0;
        int miB = (mi0 + 8) & 63;        // may be >= M: computed, discarded
        bool hasB = (mi0 + 8) < M;
        unsigned long long aA1 = 0ull, aA2 = 0ull, aB1 = 0ull, aB2 = 0ull;
        #pragma unroll 4
        for (int t = 0; t < 32; t++) {
            int c = ((t + l) & 31) << 1;   // skew -> conflict-free 64-bit LDS
            unsigned long long a2 = *(const unsigned long long*)&s_att[c];
            unsigned long long x1 = *(const unsigned long long*)&s_xlc[(l << 6) + c];
            unsigned long long x2 = *(const unsigned long long*)&s_xlc[((l + 32) << 6) + c];
            unsigned long long rA = *(const unsigned long long*)&s_xrc[(miA << 6) + c];
            unsigned long long rB = *(const unsigned long long*)&s_xrc[(miB << 6) + c];
            unsigned long long sA1, sA2, sB1, sB2;
            ADD2(sA1, rA, x1); ADD2(sA2, rA, x2);
            ADD2(sB1, rB, x1); ADD2(sB2, rB, x2);
            sA1 &= ABS2; sA2 &= ABS2; sB1 &= ABS2; sB2 &= ABS2;
            FMA2ACC(aA1, a2, sA1); FMA2ACC(aA2, a2, sA2);
            FMA2ACC(aB1, a2, sB1); FMA2ACC(aB2, a2, sB2);
        }
        // finalize e + softmax for row A (and B if real)
        float lo, hi;
        UNPACK2(lo, hi, aA1); float abA1 = lo + hi;
        UNPACK2(lo, hi, aA2); float abA2 = lo + hi;
        UNPACK2(lo, hi, aB1); float abB1 = lo + hi;
        UNPACK2(lo, hi, aB2); float abB2 = lo + hi;
        float drA = s_dr[miA];
        float drB = s_dr[miB];
        float eA1 = v1 ? fmaf(0.4f, abA1, 0.6f * (drA + dl1)) : -1e30f;
        float eA2 = v2 ? fmaf(0.4f, abA2, 0.6f * (drA + dl2)) : -1e30f;
        float eB1 = v1 ? fmaf(0.4f, abB1, 0.6f * (drB + dl1)) : -1e30f;
        float eB2 = v2 ? fmaf(0.4f, abB2, 0.6f * (drB + dl2)) : -1e30f;
        float mxA = fmaxf(eA1, eA2);
        float mxB = fmaxf(eB1, eB2);
        #pragma unroll
        for (int o = 16; o > 0; o >>= 1) {
            mxA = fmaxf(mxA, __shfl_xor_sync(0xffffffffu, mxA, o));
            mxB = fmaxf(mxB, __shfl_xor_sync(0xffffffffu, mxB, o));
        }
        float pA1 = expf(eA1 - mxA), pA2 = expf(eA2 - mxA);
        float pB1 = expf(eB1 - mxB), pB2 = expf(eB2 - mxB);
        float svA = pA1 + pA2, svB = pB1 + pB2;
        #pragma unroll
        for (int o = 16; o > 0; o >>= 1) {
            svA += __shfl_xor_sync(0xffffffffu, svA, o);
            svB += __shfl_xor_sync(0xffffffffu, svB, o);
        }
        float invA = 1.0f / svA, invB = 1.0f / svB;
        s_alpha[(miA << 6) + l] = pA1 * invA;
        s_alpha[(miA << 6) + l + 32] = pA2 * invA;
        if (hasB) {
            s_alpha[(miB << 6) + l] = pB1 * invB;
            s_alpha[(miB << 6) + l + 32] = pB2 * invB;
        }
        __syncwarp();

        // AV for rows A/B: lane owns channels c = l, l+32
        float oA1 = 0.f, oA2 = 0.f, oB1 = 0.f, oB2 = 0.f;
        for (int mj = 0; mj < M; mj++) {
            float x1 = s_xlc[(mj << 6) + l];
            float x2 = s_xlc[(mj << 6) + l + 32];
            float alA = s_alpha[(miA << 6) + mj];
            float alB = s_alpha[(miB << 6) + mj];
            oA1 = fmaf(alA, x1, oA1);
            oA2 = fmaf(alA, x2, oA2);
            oB1 = fmaf(alB, x1, oB1);
            oB2 = fmaf(alB, x2, oB2);
        }
        size_t gA = (size_t)(rowbase + s_list[miA]) * HID + hoff;
        go[gA + l] = oA1;
        go[gA + l + 32] = oA2;
        if (hasB) {
            size_t gB = (size_t)(rowbase + s_list[miB]) * HID + hoff;
            go[gB + l] = oB1;
            go[gB + l + 32] = oB2;
        }
    }
}

// ---------------- epilogue: bias + ELU + LayerNorm + residual + mask --------
__device__ __forceinline__ float block_reduce_sum_256(float v, float* red, int tid) {
    __syncthreads();
    #pragma unroll
    for (int o = 16; o > 0; o >>= 1)
        v += __shfl_xor_sync(0xffffffffu, v, o);
    if ((tid & 31) == 0) red[tid >> 5] = v;
    __syncthreads();
    float tot = 0.f;
    #pragma unroll
    for (int i = 0; i < 8; i++) tot += red[i];
    return tot;
}

__global__ __launch_bounds__(256) void epilogue_kernel(
    const float* __restrict__ go, const float* __restrict__ resid,
    const float* __restrict__ ob, const float* __restrict__ lns,
    const float* __restrict__ lnb, float* __restrict__ outp,
    int final_layer, const float* __restrict__ h0) {
    __shared__ float red[8];
    int row = blockIdx.x;
    int c = threadIdx.x;
    size_t idx = (size_t)row * HID + c;
    float v = go[idx] + ob[c];
    v = (v > 0.f) ? v : expm1f(v);                 // ELU (alpha=1)
    float sum = block_reduce_sum_256(v, red, c);
    float mu = sum * (1.0f / 256.0f);
    float d = v - mu;
    float s2 = block_reduce_sum_256(d * d, red, c);
    float var = s2 * (1.0f / 256.0f);
    float y = d * rsqrtf(var + 1e-5f) * lns[c] + lnb[c] + resid[idx];
    int gi = row >> 6, node = row & 63;
    float hv = ((g_maskbits[gi] >> node) & 1ull) ? y : 0.f;
    if (final_layer)
        outp[idx] = g_keep[gi] ? hv : h0[idx];
    else
        outp[idx] = hv;
}

// ---------------- launch ----------------------------------------------------
extern "C" void kernel_launch(void* const* d_in, const int* in_sizes, int n_in,
                              void* d_out, int out_size) {
    (void)in_sizes; (void)n_in; (void)out_size;
    const float* x   = (const float*)d_in[0];
    const unsigned char* pm = (const unsigned char*)d_in[1];
    const float* W_in = (const float*)d_in[2];
    const float* b_in = (const float*)d_in[3];
    const float* Wl  = (const float*)d_in[4];
    const float* bl  = (const float*)d_in[5];
    const float* Wr  = (const float*)d_in[6];
    const float* br  = (const float*)d_in[7];
    const float* att = (const float*)d_in[8];
    const float* ob  = (const float*)d_in[9];
    const float* lns = (const float*)d_in[10];
    const float* lnb = (const float*)d_in[11];
    float* out = (float*)d_out;

    float *h0, *hw, *xl, *xr, *go;
    cudaGetSymbolAddress((void**)&h0, g_h0);
    cudaGetSymbolAddress((void**)&hw, g_hw);
    cudaGetSymbolAddress((void**)&xl, g_xl);
    cudaGetSymbolAddress((void**)&xr, g_xr);
    cudaGetSymbolAddress((void**)&go, g_go);

    decode_mask_kernel<<<1, 256>>>(pm);

    gemm128_kernel<<<dim3(NROWS / 128, 2), 256>>>(
        x, W_in, W_in, b_in, b_in, h0, h0, DIN);

    for (int li = 0; li < 2; li++) {
        const float* hin = li ? hw : h0;
        gemm128_kernel<<<dim3(NROWS / 128, 4), 256>>>(
            hin, Wl + li * HID * HID, Wr + li * HID * HID,
            bl + li * HID, br + li * HID, xl, xr, HID);
        attn_kernel<<<dim3(NGRAPH, NHEAD), 256>>>(xl, xr, att + li * NHEAD * CH, go);
        epilogue_kernel<<<NROWS, 256>>>(go, hin, ob + li * HID, lns + li * HID,
                                        lnb + li * HID,
                                        (li == 1) ? out : hw, (li == 1) ? 1 : 0, h0);
    }
}

// round 6
// speedup vs baseline: 2.0027x; 1.0362x over previous
#include <cuda_runtime.h>
#include <cstdint>

#define HID 256
#define NNODE 64
#define NGRAPH 128
#define NROWS 8192   /* NGRAPH*NNODE */
#define DIN 512
#define NHEAD 4
#define CH 64

// ---------------- scratch (no allocations allowed -> __device__ globals) ----
__device__ float g_h0[NROWS * HID];   // projected input (full, all rows)
__device__ float g_hw[NROWS * HID];   // working hidden state (COMPACT rows)
__device__ float g_xl[NROWS * HID];   // compact
__device__ float g_xr[NROWS * HID];   // compact
__device__ float g_go[NROWS * HID];   // gat raw output (compact)
__device__ unsigned long long g_maskbits[NGRAPH];
__device__ int g_keep[NGRAPH];
__device__ int g_rowlist[NROWS];      // compact -> full row index
__device__ int g_goff[NGRAPH + 1];    // per-graph compact offsets
__device__ int g_total;               // total masked rows

// ---------------- f32x2 packed math (Blackwell FFMA2, PTX-only) -------------
#define PACK2(u, lo, hi) asm("mov.b64 %0, {%1, %2};" : "=l"(u) : "f"(lo), "f"(hi))
#define UNPACK2(lo, hi, u) asm("mov.b64 {%0, %1}, %2;" : "=f"(lo), "=f"(hi) : "l"(u))
#define FMA2ACC(d, a, b) asm("fma.rn.f32x2 %0, %1, %2, %0;" : "+l"(d) : "l"(a), "l"(b))
#define ADD2(d, a, b) asm("add.rn.f32x2 %0, %1, %2;" : "=l"(d) : "l"(a), "l"(b))

// ---------------- mask decode + compaction (dtype-robust) -------------------
__global__ void decode_mask_kernel(const unsigned char* __restrict__ pm) {
    __shared__ int flags[4];
    __shared__ unsigned char sm[NROWS];
    __shared__ unsigned long long s_mb[NGRAPH];
    __shared__ int s_cnt[NGRAPH];
    __shared__ int s_off[NGRAPH];
    int tid = threadIdx.x;
    if (tid < 4) flags[tid] = 0;
    __syncthreads();
    int loc0 = 0, loc1 = 0, loc23 = 0;
    for (int i = tid; i < NROWS; i += 256) {
        if (pm[i]) {
            int r = i & 3;
            if (r == 0) loc0 = 1;
            else if (r == 1) loc1 = 1;
            else loc23 = 1;
        }
    }
    if (loc0) atomicOr(&flags[0], 1);
    if (loc1) atomicOr(&flags[1], 1);
    if (loc23) atomicOr(&flags[2], 1);
    __syncthreads();
    int mode;
    if (flags[1]) mode = 0;          // uint8
    else if (flags[0]) mode = 1;     // int32
    else if (flags[2]) mode = 2;     // float32
    else mode = 0;
    for (int i = tid; i < NROWS; i += 256) {
        unsigned char m;
        if (mode == 0)      m = (pm[i] != 0);
        else if (mode == 1) m = (((const int*)pm)[i] != 0);
        else                m = (((const float*)pm)[i] != 0.0f);
        sm[i] = m;
    }
    __syncthreads();
    if (tid < NGRAPH) {
        unsigned long long mb = 0ull;
        int cnt = 0;
        #pragma unroll
        for (int n = 0; n < 64; n++) {
            if (sm[tid * 64 + n]) { mb |= (1ull << n); cnt++; }
        }
        s_mb[tid] = mb;
        s_cnt[tid] = cnt;
        g_maskbits[tid] = mb;
        g_keep[tid] = (cnt > 1) ? 1 : 0;
    }
    __syncthreads();
    if (tid == 0) {
        int acc = 0;
        for (int g2 = 0; g2 < NGRAPH; g2++) {
            s_off[g2] = acc;
            g_goff[g2] = acc;
            acc += s_cnt[g2];
        }
        g_goff[NGRAPH] = acc;
        g_total = acc;
    }
    __syncthreads();
    if (tid < NGRAPH) {
        int off = s_off[tid];
        unsigned long long b = s_mb[tid];
        int base = tid << 6;
        while (b) {
            g_rowlist[off++] = base + (__ffsll(b) - 1);
            b &= b - 1;
        }
    }
}

// ---------------- GEMM: 64x128 tile, 128 threads, BK=8, 8x8 microtile -------
// C[total,256] = gather(A)[*,K] @ W[K,256] + bias.
//   rowlist != null: A rows gathered via rowlist (compact output).
//   totalp  != null: runtime row count (blocks beyond it exit / guard stores).
// gridDim.y==2: both y -> W0/C0, bn=y*128.  gridDim.y==4: sel=y>>1, bn=(y&1)*128.
__global__ __launch_bounds__(128, 4) void gemm64_kernel(
    const float* __restrict__ A, const int* __restrict__ rowlist,
    const int* __restrict__ totalp,
    const float* __restrict__ W0, const float* __restrict__ W1,
    const float* __restrict__ bias0, const float* __restrict__ bias1,
    float* __restrict__ C0, float* __restrict__ C1, int K) {
    __shared__ float As[2][8][68];    // padded: conflict-free transposed stores
    __shared__ float Bs[2][8][128];
    __shared__ int s_total;
    const int Nc = 256;
    int tid = threadIdx.x;
    if (tid == 0) s_total = totalp ? *totalp : NROWS;
    __syncthreads();
    int total = s_total;
    int bm = blockIdx.x << 6;
    if (bm >= total) return;

    int sel, bn;
    if (gridDim.y == 4) { sel = blockIdx.y >> 1; bn = (blockIdx.y & 1) << 7; }
    else               { sel = 0;               bn = blockIdx.y << 7; }
    const float* W = sel ? W1 : W0;
    const float* bias = sel ? bias1 : bias0;
    float* C = sel ? C1 : C0;

    int tx = tid & 15, ty = tid >> 4;
    int arow = tid >> 1, akq = (tid & 1) << 2;
    int r_glob = bm + arow;
    int ar = rowlist ? rowlist[min(r_glob, total - 1)] : r_glob;
    const float* Ag = A + (size_t)ar * K + akq;
    int brow0 = (tid >> 5) << 1, bcol = (tid & 31) << 2;
    const float* Bg = W + (size_t)brow0 * Nc + bn + bcol;

    unsigned long long acc[8][4];
    #pragma unroll
    for (int r = 0; r < 8; r++)
        #pragma unroll
        for (int p = 0; p < 4; p++) acc[r][p] = 0ull;

    // prologue: stage tile 0
    float4 ra = *(const float4*)Ag;
    float4 rb0 = *(const float4*)Bg;
    float4 rb1 = *(const float4*)(Bg + Nc);
    As[0][akq + 0][arow] = ra.x;
    As[0][akq + 1][arow] = ra.y;
    As[0][akq + 2][arow] = ra.z;
    As[0][akq + 3][arow] = ra.w;
    *(float4*)&Bs[0][brow0][bcol] = rb0;
    *(float4*)&Bs[0][brow0 + 1][bcol] = rb1;
    __syncthreads();

    int KB = K >> 3;
    int s = 0;
    for (int kb = 0; kb < KB; kb++) {
        if (kb + 1 < KB) {
            ra = *(const float4*)(Ag + ((kb + 1) << 3));
            rb0 = *(const float4*)(Bg + (size_t)((kb + 1) << 3) * Nc);
            rb1 = *(const float4*)(Bg + (size_t)((kb + 1) << 3) * Nc + Nc);
        }
        #pragma unroll
        for (int k = 0; k < 8; k++) {
            float4 a0 = *(const float4*)&As[s][k][ty << 3];
            float4 a1 = *(const float4*)&As[s][k][(ty << 3) + 4];
            float4 b0 = *(const float4*)&Bs[s][k][tx << 3];
            float4 b1 = *(const float4*)&Bs[s][k][(tx << 3) + 4];
            unsigned long long bp0, bp1, bp2, bp3;
            PACK2(bp0, b0.x, b0.y); PACK2(bp1, b0.z, b0.w);
            PACK2(bp2, b1.x, b1.y); PACK2(bp3, b1.z, b1.w);
            unsigned long long ad[8];
            PACK2(ad[0], a0.x, a0.x); PACK2(ad[1], a0.y, a0.y);
            PACK2(ad[2], a0.z, a0.z); PACK2(ad[3], a0.w, a0.w);
            PACK2(ad[4], a1.x, a1.x); PACK2(ad[5], a1.y, a1.y);
            PACK2(ad[6], a1.z, a1.z); PACK2(ad[7], a1.w, a1.w);
            #pragma unroll
            for (int r = 0; r < 8; r++) {
                FMA2ACC(acc[r][0], ad[r], bp0);
                FMA2ACC(acc[r][1], ad[r], bp1);
                FMA2ACC(acc[r][2], ad[r], bp2);
                FMA2ACC(acc[r][3], ad[r], bp3);
            }
        }
        if (kb + 1 < KB) {
            int sn = s ^ 1;
            As[sn][akq + 0][arow] = ra.x;
            As[sn][akq + 1][arow] = ra.y;
            As[sn][akq + 2][arow] = ra.z;
            As[sn][akq + 3][arow] = ra.w;
            *(float4*)&Bs[sn][brow0][bcol] = rb0;
            *(float4*)&Bs[sn][brow0 + 1][bcol] = rb1;
            __syncthreads();
            s = sn;
        }
    }

    float4 bb0 = *(const float4*)(bias + bn + (tx << 3));
    float4 bb1 = *(const float4*)(bias + bn + (tx << 3) + 4);
    #pragma unroll
    for (int r = 0; r < 8; r++) {
        int crow = bm + (ty << 3) + r;
        if (crow < total) {
            float* cp = C + (size_t)crow * Nc + bn + (tx << 3);
            float4 o0, o1;
            UNPACK2(o0.x, o0.y, acc[r][0]); UNPACK2(o0.z, o0.w, acc[r][1]);
            UNPACK2(o1.x, o1.y, acc[r][2]); UNPACK2(o1.z, o1.w, acc[r][3]);
            o0.x += bb0.x; o0.y += bb0.y; o0.z += bb0.z; o0.w += bb0.w;
            o1.x += bb1.x; o1.y += bb1.y; o1.z += bb1.z; o1.w += bb1.w;
            *(float4*)cp = o0;
            *(float4*)(cp + 4) = o1;
        }
    }
}

// ---------------- GATv2 attention on compact rows ---------------------------
// Masked target i: allowed j = all masked nodes -> dense MxM on compact rows.
// e_ij = 0.6*(a.xr_i + a.xl_j) + 0.4*sum_c a_c*|xr_i[c]+xl_j[c]|  (exact
// leaky_relu decomposition); rank-1 parts precomputed per node.
__global__ __launch_bounds__(256) void attn_kernel(
    const float* __restrict__ xl, const float* __restrict__ xr,
    const float* __restrict__ att, float* __restrict__ go) {
    __shared__ float s_xlc[64 * 64];
    __shared__ float s_xrc[64 * 64];
    __shared__ float s_alpha[64 * 64];
    __shared__ float s_att[64];
    __shared__ float s_dl[64], s_dr[64];

    int g = blockIdx.x, h = blockIdx.y;
    int tid = threadIdx.x, w = tid >> 5, l = tid & 31;
    int goffg = g_goff[g];
    int M = g_goff[g + 1] - goffg;
    if (M == 0) return;
    int hoff = h << 6;

    if (tid < 64) s_att[tid] = att[hoff + tid];
    for (int idx = tid; idx < (M << 6); idx += 256) {
        int m = idx >> 6, c = idx & 63;
        size_t p = (size_t)(goffg + m) * HID + hoff + c;
        s_xlc[idx] = xl[p];
        s_xrc[idx] = xr[p];
    }
    __syncthreads();

    // per-node rank-1 dots (skewed c -> conflict-free)
    if (tid < M) {
        float dl = 0.f, dr = 0.f;
        #pragma unroll 8
        for (int t = 0; t < 64; t++) {
            int c = (t + tid) & 63;
            float a = s_att[c];
            dl = fmaf(a, s_xlc[(tid << 6) + c], dl);
            dr = fmaf(a, s_xrc[(tid << 6) + c], dr);
        }
        s_dl[tid] = dl;
        s_dr[tid] = dr;
    }
    __syncthreads();

    const unsigned long long ABS2 = 0x7FFFFFFF7FFFFFFFull;
    bool v1 = (l < M), v2 = (l + 32 < M);
    float dl1 = v1 ? s_dl[l] : 0.f;
    float dl2 = v2 ? s_dl[l + 32] : 0.f;

    // warp w owns rows mi % 8 == w; two rows per iter to share xl loads
    for (int mi0 = w; mi0 < M; mi0 += 16) {
        int miA = mi0;
        int miB = (mi0 + 8) & 63;        // may be dead: computed, discarded
        bool hasB = (mi0 + 8) < M;
        unsigned long long aA1 = 0ull, aA2 = 0ull, aB1 = 0ull, aB2 = 0ull;
        #pragma unroll 4
        for (int t = 0; t < 32; t++) {
            int c = ((t + l) & 31) << 1;   // skew -> conflict-free 64-bit LDS
            unsigned long long a2 = *(const unsigned long long*)&s_att[c];
            unsigned long long x1 = *(const unsigned long long*)&s_xlc[(l << 6) + c];
            unsigned long long x2 = *(const unsigned long long*)&s_xlc[((l + 32) << 6) + c];
            unsigned long long rA = *(const unsigned long long*)&s_xrc[(miA << 6) + c];
            unsigned long long rB = *(const unsigned long long*)&s_xrc[(miB << 6) + c];
            unsigned long long sA1, sA2, sB1, sB2;
            ADD2(sA1, rA, x1); ADD2(sA2, rA, x2);
            ADD2(sB1, rB, x1); ADD2(sB2, rB, x2);
            sA1 &= ABS2; sA2 &= ABS2; sB1 &= ABS2; sB2 &= ABS2;
            FMA2ACC(aA1, a2, sA1); FMA2ACC(aA2, a2, sA2);
            FMA2ACC(aB1, a2, sB1); FMA2ACC(aB2, a2, sB2);
        }
        float lo, hi;
        UNPACK2(lo, hi, aA1); float abA1 = lo + hi;
        UNPACK2(lo, hi, aA2); float abA2 = lo + hi;
        UNPACK2(lo, hi, aB1); float abB1 = lo + hi;
        UNPACK2(lo, hi, aB2); float abB2 = lo + hi;
        float drA = s_dr[miA];
        float drB = s_dr[miB];
        float eA1 = v1 ? fmaf(0.4f, abA1, 0.6f * (drA + dl1)) : -1e30f;
        float eA2 = v2 ? fmaf(0.4f, abA2, 0.6f * (drA + dl2)) : -1e30f;
        float eB1 = v1 ? fmaf(0.4f, abB1, 0.6f * (drB + dl1)) : -1e30f;
        float eB2 = v2 ? fmaf(0.4f, abB2, 0.6f * (drB + dl2)) : -1e30f;
        float mxA = fmaxf(eA1, eA2);
        float mxB = fmaxf(eB1, eB2);
        #pragma unroll
        for (int o = 16; o > 0; o >>= 1) {
            mxA = fmaxf(mxA, __shfl_xor_sync(0xffffffffu, mxA, o));
            mxB = fmaxf(mxB, __shfl_xor_sync(0xffffffffu, mxB, o));
        }
        float pA1 = expf(eA1 - mxA), pA2 = expf(eA2 - mxA);
        float pB1 = expf(eB1 - mxB), pB2 = expf(eB2 - mxB);
        float svA = pA1 + pA2, svB = pB1 + pB2;
        #pragma unroll
        for (int o = 16; o > 0; o >>= 1) {
            svA += __shfl_xor_sync(0xffffffffu, svA, o);
            svB += __shfl_xor_sync(0xffffffffu, svB, o);
        }
        float invA = 1.0f / svA, invB = 1.0f / svB;
        s_alpha[(miA << 6) + l] = pA1 * invA;
        s_alpha[(miA << 6) + l + 32] = pA2 * invA;
        if (hasB) {
            s_alpha[(miB << 6) + l] = pB1 * invB;
            s_alpha[(miB << 6) + l + 32] = pB2 * invB;
        }
        __syncwarp();

        float oA1 = 0.f, oA2 = 0.f, oB1 = 0.f, oB2 = 0.f;
        for (int mj = 0; mj < M; mj++) {
            float x1 = s_xlc[(mj << 6) + l];
            float x2 = s_xlc[(mj << 6) + l + 32];
            float alA = s_alpha[(miA << 6) + mj];
            float alB = s_alpha[(miB << 6) + mj];
            oA1 = fmaf(alA, x1, oA1);
            oA2 = fmaf(alA, x2, oA2);
            oB1 = fmaf(alB, x1, oB1);
            oB2 = fmaf(alB, x2, oB2);
        }
        size_t gA = (size_t)(goffg + miA) * HID + hoff;
        go[gA + l] = oA1;
        go[gA + l + 32] = oA2;
        if (hasB) {
            size_t gB = (size_t)(goffg + miB) * HID + hoff;
            go[gB + l] = oB1;
            go[gB + l + 32] = oB2;
        }
    }
}

// ---------------- epilogue on full rows, compact data -----------------------
__device__ __forceinline__ float block_reduce_sum_256(float v, float* red, int tid) {
    __syncthreads();
    #pragma unroll
    for (int o = 16; o > 0; o >>= 1)
        v += __shfl_xor_sync(0xffffffffu, v, o);
    if ((tid & 31) == 0) red[tid >> 5] = v;
    __syncthreads();
    float tot = 0.f;
    #pragma unroll
    for (int i = 0; i < 8; i++) tot += red[i];
    return tot;
}

__global__ __launch_bounds__(256) void epilogue_kernel(
    const float* __restrict__ go_c, const float* __restrict__ hw_c_in,
    const float* __restrict__ h0,
    const float* __restrict__ ob, const float* __restrict__ lns,
    const float* __restrict__ lnb,
    float* __restrict__ hw_c_out, float* __restrict__ outp, int final_layer) {
    __shared__ float red[8];
    int row = blockIdx.x;
    int c = threadIdx.x;
    int g = row >> 6, node = row & 63;
    unsigned long long mb = g_maskbits[g];
    bool masked = (mb >> node) & 1ull;
    size_t fidx = (size_t)row * HID + c;

    if (final_layer && !g_keep[g]) { outp[fidx] = h0[fidx]; return; }
    if (!masked) {
        if (final_layer) outp[fidx] = 0.f;
        return;
    }
    int ci = g_goff[g] + (int)__popcll(mb & ((1ull << node) - 1ull));
    size_t cidx = (size_t)ci * HID + c;
    float v = go_c[cidx] + ob[c];
    v = (v > 0.f) ? v : expm1f(v);                 // ELU (alpha=1)
    float sum = block_reduce_sum_256(v, red, c);
    float mu = sum * (1.0f / 256.0f);
    float d = v - mu;
    float s2 = block_reduce_sum_256(d * d, red, c);
    float var = s2 * (1.0f / 256.0f);
    float resid = final_layer ? hw_c_in[cidx] : h0[fidx];
    float y = d * rsqrtf(var + 1e-5f) * lns[c] + lnb[c] + resid;
    if (final_layer) outp[fidx] = y;
    else hw_c_out[cidx] = y;
}

// ---------------- launch ----------------------------------------------------
extern "C" void kernel_launch(void* const* d_in, const int* in_sizes, int n_in,
                              void* d_out, int out_size) {
    (void)in_sizes; (void)n_in; (void)out_size;
    const float* x   = (const float*)d_in[0];
    const unsigned char* pm = (const unsigned char*)d_in[1];
    const float* W_in = (const float*)d_in[2];
    const float* b_in = (const float*)d_in[3];
    const float* Wl  = (const float*)d_in[4];
    const float* bl  = (const float*)d_in[5];
    const float* Wr  = (const float*)d_in[6];
    const float* br  = (const float*)d_in[7];
    const float* att = (const float*)d_in[8];
    const float* ob  = (const float*)d_in[9];
    const float* lns = (const float*)d_in[10];
    const float* lnb = (const float*)d_in[11];
    float* out = (float*)d_out;

    float *h0, *hw, *xl, *xr, *go;
    int *rowlist, *totalp;
    cudaGetSymbolAddress((void**)&h0, g_h0);
    cudaGetSymbolAddress((void**)&hw, g_hw);
    cudaGetSymbolAddress((void**)&xl, g_xl);
    cudaGetSymbolAddress((void**)&xr, g_xr);
    cudaGetSymbolAddress((void**)&go, g_go);
    cudaGetSymbolAddress((void**)&rowlist, g_rowlist);
    cudaGetSymbolAddress((void**)&totalp, g_total);

    decode_mask_kernel<<<1, 256>>>(pm);

    // input projection (full rows): grid (128,2), 256 blocks
    gemm64_kernel<<<dim3(NROWS / 64, 2), 128>>>(
        x, nullptr, nullptr, W_in, W_in, b_in, b_in, h0, h0, DIN);

    for (int li = 0; li < 2; li++) {
        const float* hin = li ? hw : h0;                 // li=0: full+gather
        const int* rl = li ? nullptr : rowlist;          // li=1: compact direct
        gemm64_kernel<<<dim3(NROWS / 64, 4), 128>>>(
            hin, rl, totalp, Wl + li * HID * HID, Wr + li * HID * HID,
            bl + li * HID, br + li * HID, xl, xr, HID);
        attn_kernel<<<dim3(NGRAPH, NHEAD), 256>>>(xl, xr, att + li * NHEAD * CH, go);
        epilogue_kernel<<<NROWS, 256>>>(go, hw, h0, ob + li * HID, lns + li * HID,
                                        lnb + li * HID, hw,
                                        (li == 1) ? out : nullptr, (li == 1) ? 1 : 0);
    }
}

// round 9
// speedup vs baseline: 2.2091x; 1.1031x over previous
#include <cuda_runtime.h>
#include <cstdint>

#define HID 256
#define NNODE 64
#define NGRAPH 128
#define NROWS 8192   /* NGRAPH*NNODE */
#define DIN 512
#define NHEAD 4
#define CH 64

// ---------------- scratch (no allocations allowed -> __device__ globals) ----
__device__ float g_h0[NROWS * HID];   // projected input (full indexing, sparse fill)
__device__ float g_hw[NROWS * HID];   // working hidden state (COMPACT rows)
__device__ float g_xl[NROWS * HID];   // compact
__device__ float g_xr[NROWS * HID];   // compact
__device__ float g_go[NROWS * HID];   // gat raw output (compact)
__device__ unsigned long long g_maskbits[NGRAPH];
__device__ int g_keep[NGRAPH];
__device__ int g_rowlist[NROWS];      // compact -> full row index (masked rows)
__device__ int g_goff[NGRAPH + 1];    // per-graph compact offsets
__device__ int g_total;               // total masked rows
__device__ int g_extlist[NROWS];      // masked rows + rows of non-keep graphs
__device__ int g_ext_total;

// ---------------- f32x2 packed math (Blackwell FFMA2, PTX-only) -------------
#define PACK2(u, lo, hi) asm("mov.b64 %0, {%1, %2};" : "=l"(u) : "f"(lo), "f"(hi))
#define UNPACK2(lo, hi, u) asm("mov.b64 {%0, %1}, %2;" : "=f"(lo), "=f"(hi) : "l"(u))
#define FMA2ACC(d, a, b) asm("fma.rn.f32x2 %0, %1, %2, %0;" : "+l"(d) : "l"(a), "l"(b))
#define ADD2(d, a, b) asm("add.rn.f32x2 %0, %1, %2;" : "=l"(d) : "l"(a), "l"(b))

// ---------------- mask decode + compaction (dtype-robust) -------------------
__global__ void decode_mask_kernel(const unsigned char* __restrict__ pm) {
    __shared__ int flags[4];
    __shared__ unsigned char sm[NROWS];
    __shared__ unsigned long long s_mb[NGRAPH];
    __shared__ int s_cnt[NGRAPH];
    __shared__ int s_off[NGRAPH];
    __shared__ int s_eoff[NGRAPH];
    int tid = threadIdx.x;
    if (tid < 4) flags[tid] = 0;
    __syncthreads();
    int loc0 = 0, loc1 = 0, loc23 = 0;
    for (int i = tid; i < NROWS; i += 256) {
        if (pm[i]) {
            int r = i & 3;
            if (r == 0) loc0 = 1;
            else if (r == 1) loc1 = 1;
            else loc23 = 1;
        }
    }
    if (loc0) atomicOr(&flags[0], 1);
    if (loc1) atomicOr(&flags[1], 1);
    if (loc23) atomicOr(&flags[2], 1);
    __syncthreads();
    int mode;
    if (flags[1]) mode = 0;          // uint8
    else if (flags[0]) mode = 1;     // int32
    else if (flags[2]) mode = 2;     // float32
    else mode = 0;
    for (int i = tid; i < NROWS; i += 256) {
        unsigned char m;
        if (mode == 0)      m = (pm[i] != 0);
        else if (mode == 1) m = (((const int*)pm)[i] != 0);
        else                m = (((const float*)pm)[i] != 0.0f);
        sm[i] = m;
    }
    __syncthreads();
    if (tid < NGRAPH) {
        unsigned long long mb = 0ull;
        int cnt = 0;
        #pragma unroll
        for (int n = 0; n < 64; n++) {
            if (sm[tid * 64 + n]) { mb |= (1ull << n); cnt++; }
        }
        s_mb[tid] = mb;
        s_cnt[tid] = cnt;
        g_maskbits[tid] = mb;
        g_keep[tid] = (cnt > 1) ? 1 : 0;
    }
    __syncthreads();
    if (tid == 0) {
        int acc = 0, eacc = 0;
        for (int g2 = 0; g2 < NGRAPH; g2++) {
            s_off[g2] = acc;
            g_goff[g2] = acc;
            acc += s_cnt[g2];
            s_eoff[g2] = eacc;
            eacc += (s_cnt[g2] > 1) ? s_cnt[g2] : 64;   // non-keep: all rows
        }
        g_goff[NGRAPH] = acc;
        g_total = acc;
        g_ext_total = eacc;
    }
    __syncthreads();
    if (tid < NGRAPH) {
        int off = s_off[tid];
        unsigned long long b = s_mb[tid];
        int base = tid << 6;
        while (b) {
            g_rowlist[off++] = base + (__ffsll(b) - 1);
            b &= b - 1;
        }
        int eoff = s_eoff[tid];
        if (s_cnt[tid] > 1) {
            unsigned long long b2 = s_mb[tid];
            while (b2) {
                g_extlist[eoff++] = base + (__ffsll(b2) - 1);
                b2 &= b2 - 1;
            }
        } else {
            for (int n = 0; n < 64; n++) g_extlist[eoff++] = base + n;
        }
    }
}

// ---------------- GEMM: 64x128 tile, 128 threads, BK=8, 8x8 microtile -------
// C[total,256] = gather(A)[*,K] @ W[K,256] + bias, optional scatter on C.
// Microtile columns: n = {tx*4..+3} and {64+tx*4..+3}  -> every LDS.128 phase
// reads one contiguous 128B smem row (conflict-free).
__global__ __launch_bounds__(128, 4) void gemm64_kernel(
    const float* __restrict__ A, const int* __restrict__ rowlist,
    const int* __restrict__ outlist, const int* __restrict__ totalp,
    const float* __restrict__ W0, const float* __restrict__ W1,
    const float* __restrict__ bias0, const float* __restrict__ bias1,
    float* __restrict__ C0, float* __restrict__ C1, int K) {
    __shared__ float As[2][8][68];    // padded: conflict-free transposed stores
    __shared__ float Bs[2][8][128];
    __shared__ int s_total;
    const int Nc = 256;
    int tid = threadIdx.x;
    if (tid == 0) s_total = totalp ? *totalp : NROWS;
    __syncthreads();
    int total = s_total;
    int bm = blockIdx.x << 6;
    if (bm >= total) return;

    int sel, bn;
    if (gridDim.y == 4) { sel = blockIdx.y >> 1; bn = (blockIdx.y & 1) << 7; }
    else               { sel = 0;               bn = blockIdx.y << 7; }
    const float* W = sel ? W1 : W0;
    const float* bias = sel ? bias1 : bias0;
    float* C = sel ? C1 : C0;

    int tx = tid & 15, ty = tid >> 4;
    int arow = tid >> 1, akq = (tid & 1) << 2;
    int r_glob = bm + arow;
    int ar = rowlist ? rowlist[min(r_glob, total - 1)] : r_glob;
    const float* Ag = A + (size_t)ar * K + akq;
    int brow0 = (tid >> 5) << 1, bcol = (tid & 31) << 2;
    const float* Bg = W + (size_t)brow0 * Nc + bn + bcol;

    unsigned long long acc[8][4];
    #pragma unroll
    for (int r = 0; r < 8; r++)
        #pragma unroll
        for (int p = 0; p < 4; p++) acc[r][p] = 0ull;

    // prologue: stage tile 0
    float4 ra = *(const float4*)Ag;
    float4 rb0 = *(const float4*)Bg;
    float4 rb1 = *(const float4*)(Bg + Nc);
    As[0][akq + 0][arow] = ra.x;
    As[0][akq + 1][arow] = ra.y;
    As[0][akq + 2][arow] = ra.z;
    As[0][akq + 3][arow] = ra.w;
    *(float4*)&Bs[0][brow0][bcol] = rb0;
    *(float4*)&Bs[0][brow0 + 1][bcol] = rb1;
    __syncthreads();

    int KB = K >> 3;
    int s = 0;
    for (int kb = 0; kb < KB; kb++) {
        if (kb + 1 < KB) {
            ra = *(const float4*)(Ag + ((kb + 1) << 3));
            rb0 = *(const float4*)(Bg + (size_t)((kb + 1) << 3) * Nc);
            rb1 = *(const float4*)(Bg + (size_t)((kb + 1) << 3) * Nc + Nc);
        }
        #pragma unroll
        for (int k = 0; k < 8; k++) {
            float4 a0 = *(const float4*)&As[s][k][ty << 3];
            float4 a1 = *(const float4*)&As[s][k][(ty << 3) + 4];
            float4 b0 = *(const float4*)&Bs[s][k][tx << 2];         // 128B row
            float4 b1 = *(const float4*)&Bs[s][k][64 + (tx << 2)];  // 128B row
            unsigned long long bp0, bp1, bp2, bp3;
            PACK2(bp0, b0.x, b0.y); PACK2(bp1, b0.z, b0.w);
            PACK2(bp2, b1.x, b1.y); PACK2(bp3, b1.z, b1.w);
            unsigned long long ad[8];
            PACK2(ad[0], a0.x, a0.x); PACK2(ad[1], a0.y, a0.y);
            PACK2(ad[2], a0.z, a0.z); PACK2(ad[3], a0.w, a0.w);
            PACK2(ad[4], a1.x, a1.x); PACK2(ad[5], a1.y, a1.y);
            PACK2(ad[6], a1.z, a1.z); PACK2(ad[7], a1.w, a1.w);
            #pragma unroll
            for (int r = 0; r < 8; r++) {
                FMA2ACC(acc[r][0], ad[r], bp0);
                FMA2ACC(acc[r][1], ad[r], bp1);
                FMA2ACC(acc[r][2], ad[r], bp2);
                FMA2ACC(acc[r][3], ad[r], bp3);
            }
        }
        if (kb + 1 < KB) {
            int sn = s ^ 1;
            As[sn][akq + 0][arow] = ra.x;
            As[sn][akq + 1][arow] = ra.y;
            As[sn][akq + 2][arow] = ra.z;
            As[sn][akq + 3][arow] = ra.w;
            *(float4*)&Bs[sn][brow0][bcol] = rb0;
            *(float4*)&Bs[sn][brow0 + 1][bcol] = rb1;
            __syncthreads();
            s = sn;
        }
    }

    float4 bb0 = *(const float4*)(bias + bn + (tx << 2));
    float4 bb1 = *(const float4*)(bias + bn + 64 + (tx << 2));
    #pragma unroll
    for (int r = 0; r < 8; r++) {
        int crow = bm + (ty << 3) + r;
        if (crow < total) {
            int orow = outlist ? outlist[crow] : crow;
            float* cp = C + (size_t)orow * Nc + bn;
            float4 o0, o1;
            UNPACK2(o0.x, o0.y, acc[r][0]); UNPACK2(o0.z, o0.w, acc[r][1]);
            UNPACK2(o1.x, o1.y, acc[r][2]); UNPACK2(o1.z, o1.w, acc[r][3]);
            o0.x += bb0.x; o0.y += bb0.y; o0.z += bb0.z; o0.w += bb0.w;
            o1.x += bb1.x; o1.y += bb1.y; o1.z += bb1.z; o1.w += bb1.w;
            *(float4*)(cp + (tx << 2)) = o0;
            *(float4*)(cp + 64 + (tx << 2)) = o1;
        }
    }
}

// ---------------- GATv2 attention on compact rows ---------------------------
// e_ij = 0.6*(a.xr_i + a.xl_j) + 0.4*sum_c a_c*|xr_i[c]+xl_j[c]|  (exact
// leaky_relu decomposition); rank-1 parts precomputed per node.
// alpha lives per-warp (produced+consumed in-iteration) -> smem ~37KB, occ 6.
__global__ __launch_bounds__(256) void attn_kernel(
    const float* __restrict__ xl, const float* __restrict__ xr,
    const float* __restrict__ att, float* __restrict__ go) {
    __shared__ float s_xlc[64 * 64];
    __shared__ float s_xrc[64 * 64];
    __shared__ float s_alpha[8][2][64];
    __shared__ float s_att[64];
    __shared__ float s_dl[64], s_dr[64];

    int g = blockIdx.x, h = blockIdx.y;
    int tid = threadIdx.x, w = tid >> 5, l = tid & 31;
    int goffg = g_goff[g];
    int M = g_goff[g + 1] - goffg;
    if (M == 0) return;
    int hoff = h << 6;

    if (tid < 64) s_att[tid] = att[hoff + tid];
    for (int idx = tid; idx < (M << 6); idx += 256) {
        int m = idx >> 6, c = idx & 63;
        size_t p = (size_t)(goffg + m) * HID + hoff + c;
        s_xlc[idx] = xl[p];
        s_xrc[idx] = xr[p];
    }
    __syncthreads();

    // per-node rank-1 dots (skewed c -> conflict-free)
    if (tid < M) {
        float dl = 0.f, dr = 0.f;
        #pragma unroll 8
        for (int t = 0; t < 64; t++) {
            int c = (t + tid) & 63;
            float a = s_att[c];
            dl = fmaf(a, s_xlc[(tid << 6) + c], dl);
            dr = fmaf(a, s_xrc[(tid << 6) + c], dr);
        }
        s_dl[tid] = dl;
        s_dr[tid] = dr;
    }
    __syncthreads();

    const unsigned long long ABS2 = 0x7FFFFFFF7FFFFFFFull;
    bool v1 = (l < M), v2 = (l + 32 < M);
    float dl1 = v1 ? s_dl[l] : 0.f;
    float dl2 = v2 ? s_dl[l + 32] : 0.f;

    // warp w owns rows mi % 8 == w; two rows per iter to share xl loads
    for (int mi0 = w; mi0 < M; mi0 += 16) {
        int miA = mi0;
        int miB = (mi0 + 8) & 63;        // may be dead: computed, discarded
        bool hasB = (mi0 + 8) < M;
        unsigned long long aA1 = 0ull, aA2 = 0ull, aB1 = 0ull, aB2 = 0ull;
        #pragma unroll 4
        for (int t = 0; t < 32; t++) {
            int c = ((t + l) & 31) << 1;   // skew -> conflict-free 64-bit LDS
            unsigned long long a2 = *(const unsigned long long*)&s_att[c];
            unsigned long long x1 = *(const unsigned long long*)&s_xlc[(l << 6) + c];
            unsigned long long x2 = *(const unsigned long long*)&s_xlc[((l + 32) << 6) + c];
            unsigned long long rA = *(const unsigned long long*)&s_xrc[(miA << 6) + c];
            unsigned long long rB = *(const unsigned long long*)&s_xrc[(miB << 6) + c];
            unsigned long long sA1, sA2, sB1, sB2;
            ADD2(sA1, rA, x1); ADD2(sA2, rA, x2);
            ADD2(sB1, rB, x1); ADD2(sB2, rB, x2);
            sA1 &= ABS2; sA2 &= ABS2; sB1 &= ABS2; sB2 &= ABS2;
            FMA2ACC(aA1, a2, sA1); FMA2ACC(aA2, a2, sA2);
            FMA2ACC(aB1, a2, sB1); FMA2ACC(aB2, a2, sB2);
        }
        float lo, hi;
        UNPACK2(lo, hi, aA1); float abA1 = lo + hi;
        UNPACK2(lo, hi, aA2); float abA2 = lo + hi;
        UNPACK2(lo, hi, aB1); float abB1 = lo + hi;
        UNPACK2(lo, hi, aB2); float abB2 = lo + hi;
        float drA = s_dr[miA];
        float drB = s_dr[miB];
        float eA1 = v1 ? fmaf(0.4f, abA1, 0.6f * (drA + dl1)) : -1e30f;
        float eA2 = v2 ? fmaf(0.4f, abA2, 0.6f * (drA + dl2)) : -1e30f;
        float eB1 = v1 ? fmaf(0.4f, abB1, 0.6f * (drB + dl1)) : -1e30f;
        float eB2 = v2 ? fmaf(0.4f, abB2, 0.6f * (drB + dl2)) : -1e30f;
        float mxA = fmaxf(eA1, eA2);
        float mxB = fmaxf(eB1, eB2);
        #pragma unroll
        for (int o = 16; o > 0; o >>= 1) {
            mxA = fmaxf(mxA, __shfl_xor_sync(0xffffffffu, mxA, o));
            mxB = fmaxf(mxB, __shfl_xor_sync(0xffffffffu, mxB, o));
        }
        float pA1 = expf(eA1 - mxA), pA2 = expf(eA2 - mxA);
        float pB1 = expf(eB1 - mxB), pB2 = expf(eB2 - mxB);
        float svA = pA1 + pA2, svB = pB1 + pB2;
        #pragma unroll
        for (int o = 16; o > 0; o >>= 1) {
            svA += __shfl_xor_sync(0xffffffffu, svA, o);
            svB += __shfl_xor_sync(0xffffffffu, svB, o);
        }
        float invA = 1.0f / svA, invB = 1.0f / svB;
        s_alpha[w][0][l] = pA1 * invA;
        s_alpha[w][0][l + 32] = pA2 * invA;
        s_alpha[w][1][l] = pB1 * invB;
        s_alpha[w][1][l + 32] = pB2 * invB;
        __syncwarp();

        float oA1 = 0.f, oA2 = 0.f, oB1 = 0.f, oB2 = 0.f;
        for (int mj = 0; mj < M; mj++) {
            float x1 = s_xlc[(mj << 6) + l];
            float x2 = s_xlc[(mj << 6) + l + 32];
            float alA = s_alpha[w][0][mj];
            float alB = s_alpha[w][1][mj];
            oA1 = fmaf(alA, x1, oA1);
            oA2 = fmaf(alA, x2, oA2);
            oB1 = fmaf(alB, x1, oB1);
            oB2 = fmaf(alB, x2, oB2);
        }
        size_t gA = (size_t)(goffg + miA) * HID + hoff;
        go[gA + l] = oA1;
        go[gA + l + 32] = oA2;
        if (hasB) {
            size_t gB = (size_t)(goffg + miB) * HID + hoff;
            go[gB + l] = oB1;
            go[gB + l + 32] = oB2;
        }
        __syncwarp();
    }
}

// ---------------- epilogue on full rows, compact data -----------------------
__device__ __forceinline__ float block_reduce_sum_256(float v, float* red, int tid) {
    __syncthreads();
    #pragma unroll
    for (int o = 16; o > 0; o >>= 1)
        v += __shfl_xor_sync(0xffffffffu, v, o);
    if ((tid & 31) == 0) red[tid >> 5] = v;
    __syncthreads();
    float tot = 0.f;
    #pragma unroll
    for (int i = 0; i < 8; i++) tot += red[i];
    return tot;
}

__global__ __launch_bounds__(256) void epilogue_kernel(
    const float* __restrict__ go_c, const float* __restrict__ hw_c_in,
    const float* __restrict__ h0,
    const float* __restrict__ ob, const float* __restrict__ lns,
    const float* __restrict__ lnb,
    float* __restrict__ hw_c_out, float* __restrict__ outp, int final_layer) {
    __shared__ float red[8];
    int row = blockIdx.x;
    int c = threadIdx.x;
    int g = row >> 6, node = row & 63;
    unsigned long long mb = g_maskbits[g];
    bool masked = (mb >> node) & 1ull;
    size_t fidx = (size_t)row * HID + c;

    if (final_layer && !g_keep[g]) { outp[fidx] = h0[fidx]; return; }
    if (!masked) {
        if (final_layer) outp[fidx] = 0.f;
        return;
    }
    int ci = g_goff[g] + (int)__popcll(mb & ((1ull << node) - 1ull));
    size_t cidx = (size_t)ci * HID + c;
    float v = go_c[cidx] + ob[c];
    v = (v > 0.f) ? v : expm1f(v);                 // ELU (alpha=1)
    float sum = block_reduce_sum_256(v, red, c);
    float mu = sum * (1.0f / 256.0f);
    float d = v - mu;
    float s2 = block_reduce_sum_256(d * d, red, c);
    float var = s2 * (1.0f / 256.0f);
    float resid = final_layer ? hw_c_in[cidx] : h0[fidx];
    float y = d * rsqrtf(var + 1e-5f) * lns[c] + lnb[c] + resid;
    if (final_layer) outp[fidx] = y;
    else hw_c_out[cidx] = y;
}

// ---------------- launch ----------------------------------------------------
extern "C" void kernel_launch(void* const* d_in, const int* in_sizes, int n_in,
                              void* d_out, int out_size) {
    (void)in_sizes; (void)n_in; (void)out_size;
    const float* x   = (const float*)d_in[0];
    const unsigned char* pm = (const unsigned char*)d_in[1];
    const float* W_in = (const float*)d_in[2];
    const float* b_in = (const float*)d_in[3];
    const float* Wl  = (const float*)d_in[4];
    const float* bl  = (const float*)d_in[5];
    const float* Wr  = (const float*)d_in[6];
    const float* br  = (const float*)d_in[7];
    const float* att = (const float*)d_in[8];
    const float* ob  = (const float*)d_in[9];
    const float* lns = (const float*)d_in[10];
    const float* lnb = (const float*)d_in[11];
    float* out = (float*)d_out;

    float *h0, *hw, *xl, *xr, *go;
    int *rowlist, *extlist, *totalp, *ext_totalp;
    cudaGetSymbolAddress((void**)&h0, g_h0);
    cudaGetSymbolAddress((void**)&hw, g_hw);
    cudaGetSymbolAddress((void**)&xl, g_xl);
    cudaGetSymbolAddress((void**)&xr, g_xr);
    cudaGetSymbolAddress((void**)&go, g_go);
    cudaGetSymbolAddress((void**)&rowlist, g_rowlist);
    cudaGetSymbolAddress((void**)&extlist, g_extlist);
    cudaGetSymbolAddress((void**)&totalp, g_total);
    cudaGetSymbolAddress((void**)&ext_totalp, g_ext_total);

    decode_mask_kernel<<<1, 256>>>(pm);

    // input projection: only rows that are ever read (masked + non-keep graphs)
    gemm64_kernel<<<dim3(NROWS / 64, 2), 128>>>(
        x, extlist, extlist, ext_totalp, W_in, W_in, b_in, b_in, h0, h0, DIN);

    for (int li = 0; li < 2; li++) {
        const float* hin = li ? hw : h0;                 // li=0: full+gather
        const int* rl = li ? nullptr : rowlist;          // li=1: compact direct
        gemm64_kernel<<<dim3(NROWS / 64, 4), 128>>>(
            hin, rl, nullptr, totalp, Wl + li * HID * HID, Wr + li * HID * HID,
            bl + li * HID, br + li * HID, xl, xr, HID);
        attn_kernel<<<dim3(NGRAPH, NHEAD), 256>>>(xl, xr, att + li * NHEAD * CH, go);
        epilogue_kernel<<<NROWS, 256>>>(go, hw, h0, ob + li * HID, lns + li * HID,
                                        lnb + li * HID, hw,
                                        (li == 1) ? out : nullptr, (li == 1) ? 1 : 0);
    }
}